// round 14
// baseline (speedup 1.0000x reference)
#include <cuda_runtime.h>

#define BB   128
#define VV   256
#define FF   64
#define NS   4
#define NLR  64
#define NSLR 68
#define KNB  40
#define NOUT 128
#define KOUT 192

// ---------------- scratch ----------------------------------------------------
__device__ float g_mx  [BB * FF];
__device__ float g_s   [BB * VV * NS];
__device__ float g_lr  [BB * VV * NLR];
__device__ int   g_nidx[BB * VV * KNB];
__device__ float g_nw  [BB * VV * KNB];
__device__ float g_bb  [BB * NOUT];               // b_out + mx @ W_out[64:128]
__device__ float g_fpT [BB * KOUT * VV];          // transposed fp: [b][k][v]

// ---------------- packed f32x2 helpers ---------------------------------------
typedef unsigned long long ull;
__device__ __forceinline__ ull pack2(float lo, float hi) {
    ull r; asm("mov.b64 %0, {%1, %2};" : "=l"(r) : "f"(lo), "f"(hi)); return r;
}
__device__ __forceinline__ void unpack2(ull v, float& lo, float& hi) {
    asm("mov.b64 {%0, %1}, %2;" : "=f"(lo), "=f"(hi) : "l"(v));
}
__device__ __forceinline__ void fma2(ull& d, ull a, ull b) {
    asm("fma.rn.f32x2 %0, %1, %2, %0;" : "+l"(d) : "l"(a), "l"(b));
}

// ============ K_FRONT: mean + slr GEMM + out-bias + x-transpose ==============
// 2 blocks per batch: both stage full x (for mean), each does 128 GEMM rows.
#define XSP 65
#define KF_SMEM ((VV * XSP + 128 * NSLR + 64 + 256 + NSLR) * 4)
__global__ void k_front(const float* __restrict__ x,
                        const float* __restrict__ W,
                        const float* __restrict__ bias,
                        const float* __restrict__ W_out,
                        const float* __restrict__ b_out) {
    extern __shared__ float sh[];
    float* xs   = sh;                       // [256][65]
    float* Wsh  = xs + VV * XSP;            // [128][68]
    float* mean = Wsh + 128 * NSLR;         // [64]
    float* red  = mean + 64;                // [256]
    float* cc   = red + 256;                // [68]
    int b = blockIdx.x >> 1;
    int h = blockIdx.x & 1;                 // row half
    int t = threadIdx.x;

    const float* xb = x + (size_t)b * VV * FF;
    for (int e = t; e < VV * FF; e += 256) {
        int row = e >> 6, c = e & 63;
        xs[row * XSP + c] = xb[e];
    }
    for (int e = t; e < 128 * NSLR; e += 256) Wsh[e] = W[e];
    __syncthreads();

    // x-part of transposed fp: this block writes its half of v range
    {
        float* dst = g_fpT + (size_t)b * KOUT * VV + h * 128;
        for (int e = t; e < FF * 128; e += 256) {
            int k = e >> 7, r = e & 127;
            dst[k * VV + r] = xs[(h * 128 + r) * XSP + k];
        }
    }

    {
        int f = t & 63, vg = t >> 6;
        float acc = 0.f;
        #pragma unroll 8
        for (int v = vg * 64; v < vg * 64 + 64; v++) acc += xs[v * XSP + f];
        red[vg * 64 + f] = acc;
    }
    __syncthreads();
    if (t < 64) {
        float m = (red[t] + red[64 + t] + red[128 + t] + red[192 + t]) * (1.0f / VV);
        mean[t] = m;
        if (h == 0) g_mx[b * FF + t] = m;
    }
    __syncthreads();

    if (t < NSLR) {
        float acc = bias[t];
        #pragma unroll 8
        for (int k = 0; k < 64; k++) acc += mean[k] * Wsh[(64 + k) * NSLR + t];
        cc[t] = acc;
    }
    if (h == 0 && t < NOUT) {
        float acc = b_out[t];
        const float* wr = W_out + 64 * NOUT + t;
        #pragma unroll 16
        for (int k = 0; k < 64; k++) acc += mean[k] * wr[k * NOUT];
        g_bb[b * NOUT + t] = acc;
    }
    __syncthreads();

    // GEMM for 128 rows: thread = 2 rows x 17 cols
    int rg = t >> 2;                 // 0..63 -> rows h*128 + rg*2, +1
    int cg = t & 3;                  // cols cg*17..cg*17+16
    int r0 = h * 128 + rg * 2;
    float acc[2][17];
    #pragma unroll
    for (int u = 0; u < 17; u++) {
        float c0 = cc[cg * 17 + u];
        acc[0][u] = c0; acc[1][u] = c0;
    }
    const float* xr = xs + r0 * XSP;
    #pragma unroll 4
    for (int k = 0; k < 64; k++) {
        float a0 = xr[k], a1 = xr[XSP + k];
        const float* wrow = Wsh + k * NSLR + cg * 17;
        #pragma unroll
        for (int u = 0; u < 17; u++) {
            float w = wrow[u];
            acc[0][u] += a0 * w; acc[1][u] += a1 * w;
        }
    }
    #pragma unroll
    for (int q = 0; q < 2; q++) {
        int bv = b * VV + r0 + q;
        #pragma unroll
        for (int u = 0; u < 17; u++) {
            int col = cg * 17 + u;
            float v = fmaxf(acc[q][u], 0.f);
            if (col < NS) g_s [bv * NS  + col]       = v;
            else          g_lr[bv * NLR + col - NS]  = v;
        }
    }
}

// ============ K_SEL: warp-per-row top-40 by (d2, idx) ========================
__global__ void k_sel() {
    __shared__ float4 s_sh[VV];
    int b = blockIdx.x >> 5;
    int i = ((blockIdx.x & 31) << 3) + (threadIdx.x >> 5);
    int l = threadIdx.x & 31;
    if (threadIdx.x < VV)
        s_sh[threadIdx.x] = ((const float4*)g_s)[b * VV + threadIdx.x];
    __syncthreads();

    float4 sv = s_sh[i];
    float d2[8]; unsigned bits[8];
    #pragma unroll
    for (int q = 0; q < 8; q++) {
        float4 sj = s_sh[q * 32 + l];
        float dx = sv.x - sj.x, dy = sv.y - sj.y, dz = sv.z - sj.z, dw = sv.w - sj.w;
        d2[q] = dx * dx + dy * dy + dz * dz + dw * dw;
        bits[q] = __float_as_uint(d2[q]);
    }
    // binary search: smallest thr with count(bits <= thr) >= 40
    unsigned lo = 0u, hi = 0xFFFFFFFFu;
    #pragma unroll 1
    for (int it = 0; it < 32; it++) {
        unsigned mid = lo + ((hi - lo) >> 1);
        int c = 0;
        #pragma unroll
        for (int q = 0; q < 8; q++) c += (bits[q] <= mid);
        c = __reduce_add_sync(0xFFFFFFFFu, c);
        if (c >= KNB) hi = mid; else lo = mid + 1u;
    }
    unsigned thr = lo;
    int cl = 0;
    #pragma unroll
    for (int q = 0; q < 8; q++) cl += (bits[q] < thr);
    cl = __reduce_add_sync(0xFFFFFFFFu, cl);
    int need = KNB - cl;

    // tie-break index via ballot scan: need-th smallest index with bits==thr
    int jthr = VV - 1;
    {
        int cum = 0;
        bool done = false;
        #pragma unroll
        for (int q = 0; q < 8; q++) {
            unsigned mq = __ballot_sync(0xFFFFFFFFu, bits[q] == thr);
            int c = __popc(mq);
            if (!done && cum + c >= need) {
                int pos = __fns(mq, 0, need - cum);
                jthr = q * 32 + pos;
                done = true;
            }
            cum += c;
        }
    }

    int row = b * VV + i;
    int base = 0;
    #pragma unroll
    for (int q = 0; q < 8; q++) {
        int j = q * 32 + l;
        bool sel = (bits[q] < thr) || (bits[q] == thr && j <= jthr);
        unsigned bal = __ballot_sync(0xFFFFFFFFu, sel);
        if (sel) {
            int pos = base + __popc(bal & ((1u << l) - 1u));
            g_nidx[row * KNB + pos] = j;
            g_nw  [row * KNB + pos] = __expf(-10.0f * d2[q]);
        }
        base += __popc(bal);
    }
}

// ============ K_AGG: thread-per-row weighted mean/max, 2 blocks/batch ========
#define LRP 68
#define SIP 129
#define HR  128
#define KA_SMEM ((VV * LRP + 2 * KNB * SIP) * 4)
__global__ void k_agg() {
    extern __shared__ float sh[];
    float* lr_sh = sh;                       // [256][68]
    float* sw    = sh + VV * LRP;            // [40][129]
    int*   sidx  = (int*)(sw + KNB * SIP);   // [40][129]
    int b = blockIdx.x >> 1;
    int q = blockIdx.x & 1;
    int t = threadIdx.x;

    const float* lrg = g_lr + (size_t)b * VV * NLR;
    for (int e = t; e < VV * NLR; e += 256) {
        int r = e >> 6, c = e & 63;
        lr_sh[r * LRP + c] = lrg[e];
    }
    const int*   gi = g_nidx + ((size_t)b * VV + q * HR) * KNB;
    const float* gw = g_nw   + ((size_t)b * VV + q * HR) * KNB;
    for (int e = t; e < HR * KNB; e += 256) {
        int r = e / KNB, k = e - r * KNB;
        sidx[k * SIP + r] = gi[e];
        sw  [k * SIP + r] = gw[e];
    }
    __syncthreads();

    int il = t & 127;                        // local row
    int i  = q * HR + il;                    // global row in batch
    int ch = (t >> 7) * 32;                  // feature chunk base (0 or 32)

    float* dm = g_fpT + (size_t)b * KOUT * VV + (size_t)64  * VV + i;
    float* dx = g_fpT + (size_t)b * KOUT * VV + (size_t)128 * VV + i;
    #pragma unroll
    for (int cc = 0; cc < 32; cc += 16) {
        int c0 = ch + cc;
        float m[16], mx[16];
        #pragma unroll
        for (int f = 0; f < 16; f++) { m[f] = 0.f; mx[f] = 0.f; }
        for (int k = 0; k < KNB; k++) {
            int   j = sidx[k * SIP + il];
            float w = sw  [k * SIP + il];
            const float4* rowp = (const float4*)&lr_sh[j * LRP + c0];
            #pragma unroll
            for (int qq = 0; qq < 4; qq++) {
                float4 lv = rowp[qq];
                float v0 = lv.x * w, v1 = lv.y * w, v2 = lv.z * w, v3 = lv.w * w;
                m [qq*4+0] += v0; m [qq*4+1] += v1; m [qq*4+2] += v2; m [qq*4+3] += v3;
                mx[qq*4+0] = fmaxf(mx[qq*4+0], v0);
                mx[qq*4+1] = fmaxf(mx[qq*4+1], v1);
                mx[qq*4+2] = fmaxf(mx[qq*4+2], v2);
                mx[qq*4+3] = fmaxf(mx[qq*4+3], v3);
            }
        }
        #pragma unroll
        for (int f = 0; f < 16; f++) {
            dm[(c0 + f) * VV] = m[f] * (1.0f / KNB);
            dx[(c0 + f) * VV] = mx[f];
        }
    }
}

// ============ K_OUT: out = relu(fpT^T @ W + bb) ==============================
// 128 rows x 128 cols per block (grid 256), 256 threads, 2 blocks/SM.
// Thread tile: 8 rows (4 f32x2 rowpairs) x 8 cols -> halves L1 wavefronts/MAC.
#define ROWS_O 128
#define KO_SMEM ((KOUT * ROWS_O + NOUT) * 4)

#define KOUT_BODY(KIDX, W4A, W4B)                                               \
    {                                                                           \
        const float* base_ = fb + (KIDX) * ROWS_O;                              \
        ull a0 = *(const ull*)(base_);                                          \
        ull a1 = *(const ull*)(base_ + 2);                                      \
        ull a2 = *(const ull*)(base_ + 4);                                      \
        ull a3 = *(const ull*)(base_ + 6);                                      \
        ull w0 = pack2((W4A).x, (W4A).x), w1 = pack2((W4A).y, (W4A).y);         \
        ull w2 = pack2((W4A).z, (W4A).z), w3 = pack2((W4A).w, (W4A).w);         \
        ull w4 = pack2((W4B).x, (W4B).x), w5 = pack2((W4B).y, (W4B).y);         \
        ull w6 = pack2((W4B).z, (W4B).z), w7 = pack2((W4B).w, (W4B).w);         \
        fma2(acc[0][0], a0, w0); fma2(acc[1][0], a1, w0);                       \
        fma2(acc[2][0], a2, w0); fma2(acc[3][0], a3, w0);                       \
        fma2(acc[0][1], a0, w1); fma2(acc[1][1], a1, w1);                       \
        fma2(acc[2][1], a2, w1); fma2(acc[3][1], a3, w1);                       \
        fma2(acc[0][2], a0, w2); fma2(acc[1][2], a1, w2);                       \
        fma2(acc[2][2], a2, w2); fma2(acc[3][2], a3, w2);                       \
        fma2(acc[0][3], a0, w3); fma2(acc[1][3], a1, w3);                       \
        fma2(acc[2][3], a2, w3); fma2(acc[3][3], a3, w3);                       \
        fma2(acc[0][4], a0, w4); fma2(acc[1][4], a1, w4);                       \
        fma2(acc[2][4], a2, w4); fma2(acc[3][4], a3, w4);                       \
        fma2(acc[0][5], a0, w5); fma2(acc[1][5], a1, w5);                       \
        fma2(acc[2][5], a2, w5); fma2(acc[3][5], a3, w5);                       \
        fma2(acc[0][6], a0, w6); fma2(acc[1][6], a1, w6);                       \
        fma2(acc[2][6], a2, w6); fma2(acc[3][6], a3, w6);                       \
        fma2(acc[0][7], a0, w7); fma2(acc[1][7], a1, w7);                       \
        fma2(acc[2][7], a2, w7); fma2(acc[3][7], a3, w7);                       \
    }

__global__ __launch_bounds__(256, 2)
void k_out(const float* __restrict__ W,
           float* __restrict__ out) {
    extern __shared__ float sh[];
    float* fs  = sh;                     // [192][128]
    float* bbs = fs + KOUT * ROWS_O;     // [128]
    int t   = threadIdx.x;
    int bv0 = blockIdx.x * ROWS_O;
    int b   = bv0 >> 8;

    const float* src = g_fpT + (size_t)b * KOUT * VV + (bv0 & 255);
    #pragma unroll 12
    for (int e = t; e < KOUT * ROWS_O; e += 256) {
        int k = e >> 7, r = e & 127;
        fs[e] = src[k * VV + r];
    }
    if (t < NOUT) bbs[t] = g_bb[b * NOUT + t];
    __syncthreads();

    int rg = t >> 4;     // 16 rowgroups x 8 rows
    int cg = t & 15;     // 16 colgroups x 8 cols

    ull acc[4][8];       // [rowpair][col]
    #pragma unroll
    for (int c = 0; c < 8; c++) {
        float bv = bbs[cg * 8 + c];
        ull bp = pack2(bv, bv);
        #pragma unroll
        for (int rp = 0; rp < 4; rp++) acc[rp][c] = bp;
    }

    const float*  fb = fs + rg * 8;
    const float4* wp = (const float4*)(W) + cg * 2;  // two float4 per k row

    // W rows: k<64 -> row k; k>=64 -> row k+64 (mx block folded into bb).
    float4 wa = __ldg(wp), wb = __ldg(wp + 1);
    #pragma unroll 4
    for (int k = 0; k < 63; k++) {
        const float4* nx = wp + (size_t)(k + 1) * 32;
        float4 na = __ldg(nx), nb = __ldg(nx + 1);
        KOUT_BODY(k, wa, wb);
        wa = na; wb = nb;
    }
    {
        const float4* nx = wp + (size_t)128 * 32;
        float4 na = __ldg(nx), nb = __ldg(nx + 1);
        KOUT_BODY(63, wa, wb);
        wa = na; wb = nb;
    }
    #pragma unroll 4
    for (int k = 64; k < 191; k++) {
        const float4* nx = wp + (size_t)(k + 65) * 32;
        float4 na = __ldg(nx), nb = __ldg(nx + 1);
        KOUT_BODY(k, wa, wb);
        wa = na; wb = nb;
    }
    KOUT_BODY(191, wa, wb);

    #pragma unroll
    for (int rp = 0; rp < 4; rp++) {
        float lo[8], hi[8];
        #pragma unroll
        for (int c = 0; c < 8; c++) unpack2(acc[rp][c], lo[c], hi[c]);
        float4 o0a, o0b, o1a, o1b;
        o0a.x = fmaxf(lo[0], 0.f); o0a.y = fmaxf(lo[1], 0.f);
        o0a.z = fmaxf(lo[2], 0.f); o0a.w = fmaxf(lo[3], 0.f);
        o0b.x = fmaxf(lo[4], 0.f); o0b.y = fmaxf(lo[5], 0.f);
        o0b.z = fmaxf(lo[6], 0.f); o0b.w = fmaxf(lo[7], 0.f);
        o1a.x = fmaxf(hi[0], 0.f); o1a.y = fmaxf(hi[1], 0.f);
        o1a.z = fmaxf(hi[2], 0.f); o1a.w = fmaxf(hi[3], 0.f);
        o1b.x = fmaxf(hi[4], 0.f); o1b.y = fmaxf(hi[5], 0.f);
        o1b.z = fmaxf(hi[6], 0.f); o1b.w = fmaxf(hi[7], 0.f);
        int r0 = bv0 + rg * 8 + rp * 2;
        float* op0 = out + (size_t)r0 * NOUT + cg * 8;
        float* op1 = op0 + NOUT;
        ((float4*)op0)[0] = o0a; ((float4*)op0)[1] = o0b;
        ((float4*)op1)[0] = o1a; ((float4*)op1)[1] = o1b;
    }
}

// ---------------- launch ------------------------------------------------------
extern "C" void kernel_launch(void* const* d_in, const int* in_sizes, int n_in,
                              void* d_out, int out_size) {
    const float* x     = (const float*)d_in[0];
    const float* W_slr = (const float*)d_in[1];
    const float* b_slr = (const float*)d_in[2];
    const float* W_out = (const float*)d_in[3];
    const float* b_out = (const float*)d_in[4];
    float* out = (float*)d_out;

    static bool attr_done = false;
    if (!attr_done) {
        cudaFuncSetAttribute(k_front, cudaFuncAttributeMaxDynamicSharedMemorySize, KF_SMEM);
        cudaFuncSetAttribute(k_agg,   cudaFuncAttributeMaxDynamicSharedMemorySize, KA_SMEM);
        cudaFuncSetAttribute(k_out,   cudaFuncAttributeMaxDynamicSharedMemorySize, KO_SMEM);
        attr_done = true;
    }

    k_front<<<BB * 2, 256, KF_SMEM>>>(x, W_slr, b_slr, W_out, b_out);
    k_sel  <<<BB * VV / 8, 256>>>();
    k_agg  <<<BB * 2, 256, KA_SMEM>>>();
    k_out  <<<BB * VV / ROWS_O, 256, KO_SMEM>>>(W_out, out);
}

// round 15
// speedup vs baseline: 1.0190x; 1.0190x over previous
#include <cuda_runtime.h>

#define BB   128
#define VV   256
#define FF   64
#define NS   4
#define NLR  64
#define NSLR 68
#define KNB  40
#define NOUT 128
#define KOUT 192

// ---------------- scratch ----------------------------------------------------
__device__ float g_mx  [BB * FF];
__device__ float g_s   [BB * VV * NS];
__device__ float g_lr  [BB * VV * NLR];
__device__ int   g_nidx[BB * VV * KNB];
__device__ float g_nw  [BB * VV * KNB];
__device__ float g_bb  [BB * NOUT];               // b_out + mx @ W_out[64:128]
__device__ float g_fpT [BB * KOUT * VV];          // transposed fp: [b][k][v]

// ---------------- packed f32x2 helpers ---------------------------------------
typedef unsigned long long ull;
__device__ __forceinline__ ull pack2(float lo, float hi) {
    ull r; asm("mov.b64 %0, {%1, %2};" : "=l"(r) : "f"(lo), "f"(hi)); return r;
}
__device__ __forceinline__ void unpack2(ull v, float& lo, float& hi) {
    asm("mov.b64 {%0, %1}, %2;" : "=f"(lo), "=f"(hi) : "l"(v));
}
__device__ __forceinline__ void fma2(ull& d, ull a, ull b) {
    asm("fma.rn.f32x2 %0, %1, %2, %0;" : "+l"(d) : "l"(a), "l"(b));
}

// ============ K_FRONT: mean + slr GEMM + out-bias + x-transpose ==============
// 2 blocks per batch: both stage full x (for mean), each does 128 GEMM rows.
#define XSP 65
#define KF_SMEM ((VV * XSP + 128 * NSLR + 64 + 256 + NSLR) * 4)
__global__ void k_front(const float* __restrict__ x,
                        const float* __restrict__ W,
                        const float* __restrict__ bias,
                        const float* __restrict__ W_out,
                        const float* __restrict__ b_out) {
    extern __shared__ float sh[];
    float* xs   = sh;                       // [256][65]
    float* Wsh  = xs + VV * XSP;            // [128][68]
    float* mean = Wsh + 128 * NSLR;         // [64]
    float* red  = mean + 64;                // [256]
    float* cc   = red + 256;                // [68]
    int b = blockIdx.x >> 1;
    int h = blockIdx.x & 1;                 // row half
    int t = threadIdx.x;

    const float* xb = x + (size_t)b * VV * FF;
    for (int e = t; e < VV * FF; e += 256) {
        int row = e >> 6, c = e & 63;
        xs[row * XSP + c] = xb[e];
    }
    for (int e = t; e < 128 * NSLR; e += 256) Wsh[e] = W[e];
    __syncthreads();

    // x-part of transposed fp: this block writes its half of v range
    {
        float* dst = g_fpT + (size_t)b * KOUT * VV + h * 128;
        for (int e = t; e < FF * 128; e += 256) {
            int k = e >> 7, r = e & 127;
            dst[k * VV + r] = xs[(h * 128 + r) * XSP + k];
        }
    }

    {
        int f = t & 63, vg = t >> 6;
        float acc = 0.f;
        #pragma unroll 8
        for (int v = vg * 64; v < vg * 64 + 64; v++) acc += xs[v * XSP + f];
        red[vg * 64 + f] = acc;
    }
    __syncthreads();
    if (t < 64) {
        float m = (red[t] + red[64 + t] + red[128 + t] + red[192 + t]) * (1.0f / VV);
        mean[t] = m;
        if (h == 0) g_mx[b * FF + t] = m;
    }
    __syncthreads();

    if (t < NSLR) {
        float acc = bias[t];
        #pragma unroll 8
        for (int k = 0; k < 64; k++) acc += mean[k] * Wsh[(64 + k) * NSLR + t];
        cc[t] = acc;
    }
    if (h == 0 && t < NOUT) {
        float acc = b_out[t];
        const float* wr = W_out + 64 * NOUT + t;
        #pragma unroll 16
        for (int k = 0; k < 64; k++) acc += mean[k] * wr[k * NOUT];
        g_bb[b * NOUT + t] = acc;
    }
    __syncthreads();

    // GEMM for 128 rows: thread = 2 rows x 17 cols
    int rg = t >> 2;                 // 0..63 -> rows h*128 + rg*2, +1
    int cg = t & 3;                  // cols cg*17..cg*17+16
    int r0 = h * 128 + rg * 2;
    float acc[2][17];
    #pragma unroll
    for (int u = 0; u < 17; u++) {
        float c0 = cc[cg * 17 + u];
        acc[0][u] = c0; acc[1][u] = c0;
    }
    const float* xr = xs + r0 * XSP;
    #pragma unroll 4
    for (int k = 0; k < 64; k++) {
        float a0 = xr[k], a1 = xr[XSP + k];
        const float* wrow = Wsh + k * NSLR + cg * 17;
        #pragma unroll
        for (int u = 0; u < 17; u++) {
            float w = wrow[u];
            acc[0][u] += a0 * w; acc[1][u] += a1 * w;
        }
    }
    #pragma unroll
    for (int q = 0; q < 2; q++) {
        int bv = b * VV + r0 + q;
        #pragma unroll
        for (int u = 0; u < 17; u++) {
            int col = cg * 17 + u;
            float v = fmaxf(acc[q][u], 0.f);
            if (col < NS) g_s [bv * NS  + col]       = v;
            else          g_lr[bv * NLR + col - NS]  = v;
        }
    }
}

// ============ K_SEL: warp-per-row top-40 by (d2, idx) ========================
__global__ void k_sel() {
    __shared__ float4 s_sh[VV];
    int b = blockIdx.x >> 5;
    int i = ((blockIdx.x & 31) << 3) + (threadIdx.x >> 5);
    int l = threadIdx.x & 31;
    if (threadIdx.x < VV)
        s_sh[threadIdx.x] = ((const float4*)g_s)[b * VV + threadIdx.x];
    __syncthreads();

    float4 sv = s_sh[i];
    float d2[8]; unsigned bits[8];
    #pragma unroll
    for (int q = 0; q < 8; q++) {
        float4 sj = s_sh[q * 32 + l];
        float dx = sv.x - sj.x, dy = sv.y - sj.y, dz = sv.z - sj.z, dw = sv.w - sj.w;
        d2[q] = dx * dx + dy * dy + dz * dz + dw * dw;
        bits[q] = __float_as_uint(d2[q]);
    }
    // binary search: smallest thr with count(bits <= thr) >= 40
    unsigned lo = 0u, hi = 0xFFFFFFFFu;
    #pragma unroll 1
    for (int it = 0; it < 32; it++) {
        unsigned mid = lo + ((hi - lo) >> 1);
        int c = 0;
        #pragma unroll
        for (int q = 0; q < 8; q++) c += (bits[q] <= mid);
        c = __reduce_add_sync(0xFFFFFFFFu, c);
        if (c >= KNB) hi = mid; else lo = mid + 1u;
    }
    unsigned thr = lo;
    int cl = 0;
    #pragma unroll
    for (int q = 0; q < 8; q++) cl += (bits[q] < thr);
    cl = __reduce_add_sync(0xFFFFFFFFu, cl);
    int need = KNB - cl;

    // tie-break index via ballot scan: need-th smallest index with bits==thr
    int jthr = VV - 1;
    {
        int cum = 0;
        bool done = false;
        #pragma unroll
        for (int q = 0; q < 8; q++) {
            unsigned mq = __ballot_sync(0xFFFFFFFFu, bits[q] == thr);
            int c = __popc(mq);
            if (!done && cum + c >= need) {
                int pos = __fns(mq, 0, need - cum);
                jthr = q * 32 + pos;
                done = true;
            }
            cum += c;
        }
    }

    int row = b * VV + i;
    int base = 0;
    #pragma unroll
    for (int q = 0; q < 8; q++) {
        int j = q * 32 + l;
        bool sel = (bits[q] < thr) || (bits[q] == thr && j <= jthr);
        unsigned bal = __ballot_sync(0xFFFFFFFFu, sel);
        if (sel) {
            int pos = base + __popc(bal & ((1u << l) - 1u));
            g_nidx[row * KNB + pos] = j;
            g_nw  [row * KNB + pos] = __expf(-10.0f * d2[q]);
        }
        base += __popc(bal);
    }
}

// ============ K_AGG: thread-per-row weighted mean/max, 2 blocks/batch ========
#define LRP 68
#define SIP 129
#define HR  128
#define KA_SMEM ((VV * LRP + 2 * KNB * SIP) * 4)
__global__ void k_agg() {
    extern __shared__ float sh[];
    float* lr_sh = sh;                       // [256][68]
    float* sw    = sh + VV * LRP;            // [40][129]
    int*   sidx  = (int*)(sw + KNB * SIP);   // [40][129]
    int b = blockIdx.x >> 1;
    int q = blockIdx.x & 1;
    int t = threadIdx.x;

    const float* lrg = g_lr + (size_t)b * VV * NLR;
    for (int e = t; e < VV * NLR; e += 256) {
        int r = e >> 6, c = e & 63;
        lr_sh[r * LRP + c] = lrg[e];
    }
    const int*   gi = g_nidx + ((size_t)b * VV + q * HR) * KNB;
    const float* gw = g_nw   + ((size_t)b * VV + q * HR) * KNB;
    for (int e = t; e < HR * KNB; e += 256) {
        int r = e / KNB, k = e - r * KNB;
        sidx[k * SIP + r] = gi[e];
        sw  [k * SIP + r] = gw[e];
    }
    __syncthreads();

    int il = t & 127;                        // local row
    int i  = q * HR + il;                    // global row in batch
    int ch = (t >> 7) * 32;                  // feature chunk base (0 or 32)

    float* dm = g_fpT + (size_t)b * KOUT * VV + (size_t)64  * VV + i;
    float* dx = g_fpT + (size_t)b * KOUT * VV + (size_t)128 * VV + i;
    #pragma unroll
    for (int cc = 0; cc < 32; cc += 16) {
        int c0 = ch + cc;
        float m[16], mx[16];
        #pragma unroll
        for (int f = 0; f < 16; f++) { m[f] = 0.f; mx[f] = 0.f; }
        for (int k = 0; k < KNB; k++) {
            int   j = sidx[k * SIP + il];
            float w = sw  [k * SIP + il];
            const float4* rowp = (const float4*)&lr_sh[j * LRP + c0];
            #pragma unroll
            for (int qq = 0; qq < 4; qq++) {
                float4 lv = rowp[qq];
                float v0 = lv.x * w, v1 = lv.y * w, v2 = lv.z * w, v3 = lv.w * w;
                m [qq*4+0] += v0; m [qq*4+1] += v1; m [qq*4+2] += v2; m [qq*4+3] += v3;
                mx[qq*4+0] = fmaxf(mx[qq*4+0], v0);
                mx[qq*4+1] = fmaxf(mx[qq*4+1], v1);
                mx[qq*4+2] = fmaxf(mx[qq*4+2], v2);
                mx[qq*4+3] = fmaxf(mx[qq*4+3], v3);
            }
        }
        #pragma unroll
        for (int f = 0; f < 16; f++) {
            dm[(c0 + f) * VV] = m[f] * (1.0f / KNB);
            dx[(c0 + f) * VV] = mx[f];
        }
    }
}

// ============ K_OUT: out = relu(fpT^T @ W + bb), prefetched W ================
// 32 rows x 128 cols per block, 1024 blocks (single wave @7/SM), 128 threads.
// A rowpairs loaded as ulonglong2 (LDS.128): 2 wavefronts/k instead of 4.
#define ROWS_O 32
#define KO_SMEM ((KOUT * ROWS_O + NOUT) * 4)

#define KOUT_BODY(KIDX, W4)                                                     \
    {                                                                           \
        const float* base_ = fb + (KIDX) * ROWS_O;                              \
        ulonglong2 p01 = *(const ulonglong2*)(base_);                           \
        ulonglong2 p23 = *(const ulonglong2*)(base_ + 4);                       \
        ull a0 = p01.x, a1 = p01.y, a2 = p23.x, a3 = p23.y;                     \
        ull w0 = pack2((W4).x, (W4).x), w1 = pack2((W4).y, (W4).y);             \
        ull w2 = pack2((W4).z, (W4).z), w3 = pack2((W4).w, (W4).w);             \
        fma2(acc[0][0], a0, w0); fma2(acc[1][0], a1, w0);                       \
        fma2(acc[2][0], a2, w0); fma2(acc[3][0], a3, w0);                       \
        fma2(acc[0][1], a0, w1); fma2(acc[1][1], a1, w1);                       \
        fma2(acc[2][1], a2, w1); fma2(acc[3][1], a3, w1);                       \
        fma2(acc[0][2], a0, w2); fma2(acc[1][2], a1, w2);                       \
        fma2(acc[2][2], a2, w2); fma2(acc[3][2], a3, w2);                       \
        fma2(acc[0][3], a0, w3); fma2(acc[1][3], a1, w3);                       \
        fma2(acc[2][3], a2, w3); fma2(acc[3][3], a3, w3);                       \
    }

__global__ __launch_bounds__(128, 7)
void k_out(const float* __restrict__ W,
           float* __restrict__ out) {
    extern __shared__ float sh[];
    float* fs  = sh;                     // [192][32]
    float* bbs = fs + KOUT * ROWS_O;     // [128]
    int t   = threadIdx.x;
    int bv0 = blockIdx.x * ROWS_O;
    int b   = bv0 >> 8;

    const float* src = g_fpT + (size_t)b * KOUT * VV + (bv0 & 255);
    #pragma unroll 12
    for (int e = t; e < KOUT * ROWS_O; e += 128) {
        int k = e >> 5, r = e & 31;
        fs[e] = src[k * VV + r];
    }
    bbs[t] = g_bb[b * NOUT + t];
    __syncthreads();

    int rg = t >> 5;     // 4 rowgroups x 8 rows
    int cg = t & 31;     // 32 colgroups x 4 cols

    ull acc[4][4];       // [rowpair][col]
    #pragma unroll
    for (int c = 0; c < 4; c++) {
        float bv = bbs[cg * 4 + c];
        ull bp = pack2(bv, bv);
        #pragma unroll
        for (int rp = 0; rp < 4; rp++) acc[rp][c] = bp;
    }

    const float*  fb = fs + rg * 8;
    const float4* wp = (const float4*)(W) + cg;

    // W rows: k<64 -> row k; k>=64 -> row k+64 (mx block folded into bb).
    float4 w4 = __ldg(wp);                            // row 0
    #pragma unroll 8
    for (int k = 0; k < 63; k++) {
        float4 wn = __ldg(wp + (size_t)(k + 1) * 32);
        KOUT_BODY(k, w4);
        w4 = wn;
    }
    {
        float4 wn = __ldg(wp + (size_t)128 * 32);
        KOUT_BODY(63, w4);
        w4 = wn;
    }
    #pragma unroll 8
    for (int k = 64; k < 191; k++) {
        float4 wn = __ldg(wp + (size_t)(k + 65) * 32);
        KOUT_BODY(k, w4);
        w4 = wn;
    }
    KOUT_BODY(191, w4);

    #pragma unroll
    for (int rp = 0; rp < 4; rp++) {
        float lo0, hi0, lo1, hi1, lo2, hi2, lo3, hi3;
        unpack2(acc[rp][0], lo0, hi0);
        unpack2(acc[rp][1], lo1, hi1);
        unpack2(acc[rp][2], lo2, hi2);
        unpack2(acc[rp][3], lo3, hi3);
        float4 o0, o1;
        o0.x = fmaxf(lo0, 0.f); o0.y = fmaxf(lo1, 0.f);
        o0.z = fmaxf(lo2, 0.f); o0.w = fmaxf(lo3, 0.f);
        o1.x = fmaxf(hi0, 0.f); o1.y = fmaxf(hi1, 0.f);
        o1.z = fmaxf(hi2, 0.f); o1.w = fmaxf(hi3, 0.f);
        int r0 = bv0 + rg * 8 + rp * 2;
        *(float4*)(out + (size_t)r0 * NOUT + cg * 4)       = o0;
        *(float4*)(out + (size_t)(r0 + 1) * NOUT + cg * 4) = o1;
    }
}

// ---------------- launch ------------------------------------------------------
extern "C" void kernel_launch(void* const* d_in, const int* in_sizes, int n_in,
                              void* d_out, int out_size) {
    const float* x     = (const float*)d_in[0];
    const float* W_slr = (const float*)d_in[1];
    const float* b_slr = (const float*)d_in[2];
    const float* W_out = (const float*)d_in[3];
    const float* b_out = (const float*)d_in[4];
    float* out = (float*)d_out;

    static bool attr_done = false;
    if (!attr_done) {
        cudaFuncSetAttribute(k_front, cudaFuncAttributeMaxDynamicSharedMemorySize, KF_SMEM);
        cudaFuncSetAttribute(k_agg,   cudaFuncAttributeMaxDynamicSharedMemorySize, KA_SMEM);
        cudaFuncSetAttribute(k_out,   cudaFuncAttributeMaxDynamicSharedMemorySize, KO_SMEM);
        attr_done = true;
    }

    k_front<<<BB * 2, 256, KF_SMEM>>>(x, W_slr, b_slr, W_out, b_out);
    k_sel  <<<BB * VV / 8, 256>>>();
    k_agg  <<<BB * 2, 256, KA_SMEM>>>();
    k_out  <<<BB * VV / ROWS_O, 128, KO_SMEM>>>(W_out, out);
}

// round 16
// speedup vs baseline: 1.0853x; 1.0651x over previous
#include <cuda_runtime.h>

#define BB   128
#define VV   256
#define FF   64
#define NS   4
#define NLR  64
#define NSLR 68
#define KNB  40
#define NOUT 128
#define KOUT 192

// ---------------- scratch ----------------------------------------------------
__device__ float g_mx  [BB * FF];
__device__ float g_s   [BB * VV * NS];
__device__ float g_lr  [BB * VV * NLR];
__device__ int   g_nidx[BB * VV * KNB];
__device__ float g_nw  [BB * VV * KNB];
__device__ float g_bb  [BB * NOUT];               // b_out + mx @ W_out[64:128]
__device__ float g_fpT [BB * KOUT * VV];          // transposed fp: [b][k][v]

// ---------------- packed f32x2 helpers ---------------------------------------
typedef unsigned long long ull;
__device__ __forceinline__ ull pack2(float lo, float hi) {
    ull r; asm("mov.b64 %0, {%1, %2};" : "=l"(r) : "f"(lo), "f"(hi)); return r;
}
__device__ __forceinline__ void unpack2(ull v, float& lo, float& hi) {
    asm("mov.b64 {%0, %1}, %2;" : "=f"(lo), "=f"(hi) : "l"(v));
}
__device__ __forceinline__ void fma2(ull& d, ull a, ull b) {
    asm("fma.rn.f32x2 %0, %1, %2, %0;" : "+l"(d) : "l"(a), "l"(b));
}
__device__ __forceinline__ ull mul2(ull a, ull b) {
    ull r; asm("mul.rn.f32x2 %0, %1, %2;" : "=l"(r) : "l"(a), "l"(b)); return r;
}

// ============ K_FRONT: mean + slr GEMM + out-bias + x-transpose ==============
// 2 blocks per batch: both stage full x (for mean), each does 128 GEMM rows.
#define XSP 65
#define KF_SMEM ((VV * XSP + 128 * NSLR + 64 + 256 + NSLR) * 4)
__global__ void k_front(const float* __restrict__ x,
                        const float* __restrict__ W,
                        const float* __restrict__ bias,
                        const float* __restrict__ W_out,
                        const float* __restrict__ b_out) {
    extern __shared__ float sh[];
    float* xs   = sh;                       // [256][65]
    float* Wsh  = xs + VV * XSP;            // [128][68]
    float* mean = Wsh + 128 * NSLR;         // [64]
    float* red  = mean + 64;                // [256]
    float* cc   = red + 256;                // [68]
    int b = blockIdx.x >> 1;
    int h = blockIdx.x & 1;                 // row half
    int t = threadIdx.x;

    const float* xb = x + (size_t)b * VV * FF;
    for (int e = t; e < VV * FF; e += 256) {
        int row = e >> 6, c = e & 63;
        xs[row * XSP + c] = xb[e];
    }
    for (int e = t; e < 128 * NSLR; e += 256) Wsh[e] = W[e];
    __syncthreads();

    // x-part of transposed fp: this block writes its half of v range
    {
        float* dst = g_fpT + (size_t)b * KOUT * VV + h * 128;
        for (int e = t; e < FF * 128; e += 256) {
            int k = e >> 7, r = e & 127;
            dst[k * VV + r] = xs[(h * 128 + r) * XSP + k];
        }
    }

    {
        int f = t & 63, vg = t >> 6;
        float acc = 0.f;
        #pragma unroll 8
        for (int v = vg * 64; v < vg * 64 + 64; v++) acc += xs[v * XSP + f];
        red[vg * 64 + f] = acc;
    }
    __syncthreads();
    if (t < 64) {
        float m = (red[t] + red[64 + t] + red[128 + t] + red[192 + t]) * (1.0f / VV);
        mean[t] = m;
        if (h == 0) g_mx[b * FF + t] = m;
    }
    __syncthreads();

    if (t < NSLR) {
        float acc = bias[t];
        #pragma unroll 8
        for (int k = 0; k < 64; k++) acc += mean[k] * Wsh[(64 + k) * NSLR + t];
        cc[t] = acc;
    }
    if (h == 0 && t < NOUT) {
        float acc = b_out[t];
        const float* wr = W_out + 64 * NOUT + t;
        #pragma unroll 16
        for (int k = 0; k < 64; k++) acc += mean[k] * wr[k * NOUT];
        g_bb[b * NOUT + t] = acc;
    }
    __syncthreads();

    // GEMM for 128 rows: thread = 2 rows x 17 cols
    int rg = t >> 2;                 // 0..63 -> rows h*128 + rg*2, +1
    int cg = t & 3;                  // cols cg*17..cg*17+16
    int r0 = h * 128 + rg * 2;
    float acc[2][17];
    #pragma unroll
    for (int u = 0; u < 17; u++) {
        float c0 = cc[cg * 17 + u];
        acc[0][u] = c0; acc[1][u] = c0;
    }
    const float* xr = xs + r0 * XSP;
    #pragma unroll 4
    for (int k = 0; k < 64; k++) {
        float a0 = xr[k], a1 = xr[XSP + k];
        const float* wrow = Wsh + k * NSLR + cg * 17;
        #pragma unroll
        for (int u = 0; u < 17; u++) {
            float w = wrow[u];
            acc[0][u] += a0 * w; acc[1][u] += a1 * w;
        }
    }
    #pragma unroll
    for (int q = 0; q < 2; q++) {
        int bv = b * VV + r0 + q;
        #pragma unroll
        for (int u = 0; u < 17; u++) {
            int col = cg * 17 + u;
            float v = fmaxf(acc[q][u], 0.f);
            if (col < NS) g_s [bv * NS  + col]       = v;
            else          g_lr[bv * NLR + col - NS]  = v;
        }
    }
}

// ============ K_SEL: warp-per-row top-40 by (d2, idx) ========================
__global__ void k_sel() {
    __shared__ float4 s_sh[VV];
    int b = blockIdx.x >> 5;
    int i = ((blockIdx.x & 31) << 3) + (threadIdx.x >> 5);
    int l = threadIdx.x & 31;
    if (threadIdx.x < VV)
        s_sh[threadIdx.x] = ((const float4*)g_s)[b * VV + threadIdx.x];
    __syncthreads();

    float4 sv = s_sh[i];
    float d2[8]; unsigned bits[8];
    #pragma unroll
    for (int q = 0; q < 8; q++) {
        float4 sj = s_sh[q * 32 + l];
        float dx = sv.x - sj.x, dy = sv.y - sj.y, dz = sv.z - sj.z, dw = sv.w - sj.w;
        d2[q] = dx * dx + dy * dy + dz * dz + dw * dw;
        bits[q] = __float_as_uint(d2[q]);
    }
    // binary search: smallest thr with count(bits <= thr) >= 40
    unsigned lo = 0u, hi = 0xFFFFFFFFu;
    #pragma unroll 1
    for (int it = 0; it < 32; it++) {
        unsigned mid = lo + ((hi - lo) >> 1);
        int c = 0;
        #pragma unroll
        for (int q = 0; q < 8; q++) c += (bits[q] <= mid);
        c = __reduce_add_sync(0xFFFFFFFFu, c);
        if (c >= KNB) hi = mid; else lo = mid + 1u;
    }
    unsigned thr = lo;
    int cl = 0;
    #pragma unroll
    for (int q = 0; q < 8; q++) cl += (bits[q] < thr);
    cl = __reduce_add_sync(0xFFFFFFFFu, cl);
    int need = KNB - cl;

    // tie-break index via ballot scan: need-th smallest index with bits==thr
    int jthr = VV - 1;
    {
        int cum = 0;
        bool done = false;
        #pragma unroll
        for (int q = 0; q < 8; q++) {
            unsigned mq = __ballot_sync(0xFFFFFFFFu, bits[q] == thr);
            int c = __popc(mq);
            if (!done && cum + c >= need) {
                int pos = __fns(mq, 0, need - cum);
                jthr = q * 32 + pos;
                done = true;
            }
            cum += c;
        }
    }

    int row = b * VV + i;
    int base = 0;
    #pragma unroll
    for (int q = 0; q < 8; q++) {
        int j = q * 32 + l;
        bool sel = (bits[q] < thr) || (bits[q] == thr && j <= jthr);
        unsigned bal = __ballot_sync(0xFFFFFFFFu, sel);
        if (sel) {
            int pos = base + __popc(bal & ((1u << l) - 1u));
            g_nidx[row * KNB + pos] = j;
            g_nw  [row * KNB + pos] = __expf(-10.0f * d2[q]);
        }
        base += __popc(bal);
    }
}

// ============ K_AGG: conflict-free warp-gather, 2 blocks/batch ===============
// 2 blocks per batch (128 rows each), 256 threads = 8 warps x 16 rows.
// Lane l owns feature pair (2l, 2l+1): gather lr_sh[j*66 + 2l] is consecutive
// LDS.64 across the warp (stride-66 rows -> conflict-free at 8B granularity).
// idx (pre-scaled byte offset) and weight fused in one broadcast LDS.64.
// 4 rows interleaved per inner pass = 4 independent gather chains (ILP).
#define LRP2 66
#define KA_SMEM ((VV * LRP2) * 4 + 128 * KNB * 8)
__global__ void k_agg() {
    extern __shared__ float sh[];
    float* lr_sh = sh;                            // [256][66]
    ull*   pairs = (ull*)(sh + VV * LRP2);        // [128][40] (off, w)
    int b = blockIdx.x >> 1;
    int q = blockIdx.x & 1;
    int t = threadIdx.x;
    int w = t >> 5, l = t & 31;

    const float* lrg = g_lr + (size_t)b * VV * NLR;
    #pragma unroll 8
    for (int e = t; e < VV * NLR; e += 256) {
        int r = e >> 6, c = e & 63;
        lr_sh[r * LRP2 + c] = lrg[e];
    }
    {
        const int*   gi = g_nidx + ((size_t)b * VV + q * 128) * KNB;
        const float* gw = g_nw   + ((size_t)b * VV + q * 128) * KNB;
        #pragma unroll
        for (int e = t; e < 128 * KNB; e += 256) {
            unsigned off = (unsigned)gi[e] * (LRP2 * 4);
            pairs[e] = (ull)off | ((ull)__float_as_uint(gw[e]) << 32);
        }
    }
    __syncthreads();

    const char* lrb = (const char*)lr_sh + 8 * l;
    float* basep = g_fpT + (size_t)b * KOUT * VV;
    float* dm0 = basep + (size_t)(64  + 2 * l) * VV;
    float* dm1 = dm0 + VV;
    float* dx0 = basep + (size_t)(128 + 2 * l) * VV;
    float* dx1 = dx0 + VV;

    #pragma unroll 1
    for (int g4 = 0; g4 < 4; g4++) {
        int r0 = w * 16 + g4 * 4;                 // local row base (of 128)
        const ull* pp = pairs + r0 * KNB;
        ull   am[4] = {0ull, 0ull, 0ull, 0ull};
        float mx[8];
        #pragma unroll
        for (int z = 0; z < 8; z++) mx[z] = 0.f;

        #pragma unroll 2
        for (int k = 0; k < KNB; k++) {
            #pragma unroll
            for (int rr = 0; rr < 4; rr++) {
                ull p = pp[rr * KNB + k];         // broadcast LDS.64
                float offf, wkf; unpack2(p, offf, wkf);
                int off = __float_as_int(offf);   // byte offset of row j
                ull w2 = pack2(wkf, wkf);
                ull v  = *(const ull*)(lrb + off);// conflict-free gather LDS.64
                fma2(am[rr], v, w2);
                ull vw = mul2(v, w2);
                float p0, p1; unpack2(vw, p0, p1);
                mx[rr * 2]     = fmaxf(mx[rr * 2],     p0);
                mx[rr * 2 + 1] = fmaxf(mx[rr * 2 + 1], p1);
            }
        }

        int iv = q * 128 + r0;                    // global v index (16B aligned)
        float m0[4], m1[4];
        #pragma unroll
        for (int rr = 0; rr < 4; rr++) {
            float lo, hi; unpack2(am[rr], lo, hi);
            m0[rr] = lo * (1.0f / KNB);
            m1[rr] = hi * (1.0f / KNB);
        }
        *(float4*)(dm0 + iv) = make_float4(m0[0], m0[1], m0[2], m0[3]);
        *(float4*)(dm1 + iv) = make_float4(m1[0], m1[1], m1[2], m1[3]);
        *(float4*)(dx0 + iv) = make_float4(mx[0], mx[2], mx[4], mx[6]);
        *(float4*)(dx1 + iv) = make_float4(mx[1], mx[3], mx[5], mx[7]);
    }
}

// ============ K_OUT: out = relu(fpT^T @ W + bb), prefetched W ================
// 32 rows x 128 cols per block, 1024 blocks (single wave @7/SM), 128 threads.
#define ROWS_O 32
#define KO_SMEM ((KOUT * ROWS_O + NOUT) * 4)

#define KOUT_BODY(KIDX, W4)                                                     \
    {                                                                           \
        const float* base_ = fb + (KIDX) * ROWS_O;                              \
        ulonglong2 p01 = *(const ulonglong2*)(base_);                           \
        ulonglong2 p23 = *(const ulonglong2*)(base_ + 4);                       \
        ull a0 = p01.x, a1 = p01.y, a2 = p23.x, a3 = p23.y;                     \
        ull w0 = pack2((W4).x, (W4).x), w1 = pack2((W4).y, (W4).y);             \
        ull w2 = pack2((W4).z, (W4).z), w3 = pack2((W4).w, (W4).w);             \
        fma2(acc[0][0], a0, w0); fma2(acc[1][0], a1, w0);                       \
        fma2(acc[2][0], a2, w0); fma2(acc[3][0], a3, w0);                       \
        fma2(acc[0][1], a0, w1); fma2(acc[1][1], a1, w1);                       \
        fma2(acc[2][1], a2, w1); fma2(acc[3][1], a3, w1);                       \
        fma2(acc[0][2], a0, w2); fma2(acc[1][2], a1, w2);                       \
        fma2(acc[2][2], a2, w2); fma2(acc[3][2], a3, w2);                       \
        fma2(acc[0][3], a0, w3); fma2(acc[1][3], a1, w3);                       \
        fma2(acc[2][3], a2, w3); fma2(acc[3][3], a3, w3);                       \
    }

__global__ __launch_bounds__(128, 7)
void k_out(const float* __restrict__ W,
           float* __restrict__ out) {
    extern __shared__ float sh[];
    float* fs  = sh;                     // [192][32]
    float* bbs = fs + KOUT * ROWS_O;     // [128]
    int t   = threadIdx.x;
    int bv0 = blockIdx.x * ROWS_O;
    int b   = bv0 >> 8;

    const float* src = g_fpT + (size_t)b * KOUT * VV + (bv0 & 255);
    #pragma unroll 12
    for (int e = t; e < KOUT * ROWS_O; e += 128) {
        int k = e >> 5, r = e & 31;
        fs[e] = src[k * VV + r];
    }
    bbs[t] = g_bb[b * NOUT + t];
    __syncthreads();

    int rg = t >> 5;     // 4 rowgroups x 8 rows
    int cg = t & 31;     // 32 colgroups x 4 cols

    ull acc[4][4];       // [rowpair][col]
    #pragma unroll
    for (int c = 0; c < 4; c++) {
        float bv = bbs[cg * 4 + c];
        ull bp = pack2(bv, bv);
        #pragma unroll
        for (int rp = 0; rp < 4; rp++) acc[rp][c] = bp;
    }

    const float*  fb = fs + rg * 8;
    const float4* wp = (const float4*)(W) + cg;

    // W rows: k<64 -> row k; k>=64 -> row k+64 (mx block folded into bb).
    float4 w4 = __ldg(wp);                            // row 0
    #pragma unroll 8
    for (int k = 0; k < 63; k++) {
        float4 wn = __ldg(wp + (size_t)(k + 1) * 32);
        KOUT_BODY(k, w4);
        w4 = wn;
    }
    {
        float4 wn = __ldg(wp + (size_t)128 * 32);
        KOUT_BODY(63, w4);
        w4 = wn;
    }
    #pragma unroll 8
    for (int k = 64; k < 191; k++) {
        float4 wn = __ldg(wp + (size_t)(k + 65) * 32);
        KOUT_BODY(k, w4);
        w4 = wn;
    }
    KOUT_BODY(191, w4);

    #pragma unroll
    for (int rp = 0; rp < 4; rp++) {
        float lo0, hi0, lo1, hi1, lo2, hi2, lo3, hi3;
        unpack2(acc[rp][0], lo0, hi0);
        unpack2(acc[rp][1], lo1, hi1);
        unpack2(acc[rp][2], lo2, hi2);
        unpack2(acc[rp][3], lo3, hi3);
        float4 o0, o1;
        o0.x = fmaxf(lo0, 0.f); o0.y = fmaxf(lo1, 0.f);
        o0.z = fmaxf(lo2, 0.f); o0.w = fmaxf(lo3, 0.f);
        o1.x = fmaxf(hi0, 0.f); o1.y = fmaxf(hi1, 0.f);
        o1.z = fmaxf(hi2, 0.f); o1.w = fmaxf(hi3, 0.f);
        int r0 = bv0 + rg * 8 + rp * 2;
        *(float4*)(out + (size_t)r0 * NOUT + cg * 4)       = o0;
        *(float4*)(out + (size_t)(r0 + 1) * NOUT + cg * 4) = o1;
    }
}

// ---------------- launch ------------------------------------------------------
extern "C" void kernel_launch(void* const* d_in, const int* in_sizes, int n_in,
                              void* d_out, int out_size) {
    const float* x     = (const float*)d_in[0];
    const float* W_slr = (const float*)d_in[1];
    const float* b_slr = (const float*)d_in[2];
    const float* W_out = (const float*)d_in[3];
    const float* b_out = (const float*)d_in[4];
    float* out = (float*)d_out;

    static bool attr_done = false;
    if (!attr_done) {
        cudaFuncSetAttribute(k_front, cudaFuncAttributeMaxDynamicSharedMemorySize, KF_SMEM);
        cudaFuncSetAttribute(k_agg,   cudaFuncAttributeMaxDynamicSharedMemorySize, KA_SMEM);
        cudaFuncSetAttribute(k_out,   cudaFuncAttributeMaxDynamicSharedMemorySize, KO_SMEM);
        attr_done = true;
    }

    k_front<<<BB * 2, 256, KF_SMEM>>>(x, W_slr, b_slr, W_out, b_out);
    k_sel  <<<BB * VV / 8, 256>>>();
    k_agg  <<<BB * 2, 256, KA_SMEM>>>();
    k_out  <<<BB * VV / ROWS_O, 128, KO_SMEM>>>(W_out, out);
}